// round 11
// baseline (speedup 1.0000x reference)
#include <cuda_runtime.h>
#include <cuda_fp16.h>

// Problem constants
#define T_TOTAL 4096
#define LAYERS  8
#define HIDDEN  1024
#define G4      4096
#define LETTERS 100
#define NCTA    128
#define TPB     256
#define NCELLS  (T_TOTAL * LAYERS)   // 32768
#define SMEM_LAYERS 3
#define WSMEM_BYTES (SMEM_LAYERS * 32 * HIDDEN * 2)   // 196608
#define NLINES  8
#define CTAS_PER_LINE (NCTA / NLINES)   // 16

// ---------------------------------------------------------------------------
// Device scratch
// ---------------------------------------------------------------------------
__device__ float g_gin[(size_t)T_TOTAL * LAYERS * G4];          // 512 MB input projections
__device__ __half g_w2[(size_t)LAYERS * NCTA * 32 * HIDDEN];    // 64 MB fp16 W_hh, mma A-fragment layout
__device__ __align__(16) __half g_hh[2][NCTA * 8];              // fp16 hidden state, parity buffered
__device__ __align__(16) float g_c[HIDDEN];                     // final cell state
__device__ unsigned g_fin;                                      // final-round counter

struct __align__(128) CtrLine { unsigned v; unsigned pad[31]; };
__device__ CtrLine g_ctrs[NLINES];   // line L counts CTAs [16L,16L+16)

__device__ __forceinline__ unsigned ld_acquire_u32(const unsigned* p) {
    unsigned v;
    asm volatile("ld.acquire.gpu.global.u32 %0, [%1];" : "=r"(v) : "l"(p) : "memory");
    return v;
}
__device__ __forceinline__ void red_release_add(unsigned* p, unsigned v) {
    asm volatile("red.release.gpu.global.add.u32 [%0], %1;" :: "l"(p), "r"(v) : "memory");
}
__device__ __forceinline__ float tanh_approx(float x) {
    float y;
    asm("tanh.approx.f32 %0, %1;" : "=f"(y) : "f"(x));
    return y;
}
__device__ __forceinline__ float sigmoid_fast(float x) {
    return 0.5f + 0.5f * tanh_approx(0.5f * x);
}
__device__ __forceinline__ void mma_16x8x16(float& d0, float& d1, float& d2, float& d3,
                                            uint4 a, unsigned b0, unsigned b1) {
    asm volatile(
        "mma.sync.aligned.m16n8k16.row.col.f32.f16.f16.f32 "
        "{%0,%1,%2,%3}, {%4,%5,%6,%7}, {%8,%9}, {%0,%1,%2,%3};"
        : "+f"(d0), "+f"(d1), "+f"(d2), "+f"(d3)
        : "r"(a.x), "r"(a.y), "r"(a.z), "r"(a.w), "r"(b0), "r"(b1));
}

// ---------------------------------------------------------------------------
// Phase 1a: gin[cell][row] = W_ih@x_t + b_ih + b_hh; reset state.
// ---------------------------------------------------------------------------
__global__ void precompute_kernel(const float* __restrict__ website,
                                  const float* __restrict__ payload,
                                  const float* __restrict__ W_ih,
                                  const float* __restrict__ b_ih,
                                  const float* __restrict__ b_hh) {
    __shared__ float Xsm[16 * LETTERS];
    const int rt = blockIdx.x;
    const int l  = blockIdx.y;
    const int t0 = blockIdx.z * 16;

    for (int idx = threadIdx.x; idx < 16 * LETTERS; idx += 128) {
        int tt = idx / LETTERS, k = idx % LETTERS;
        int t = t0 + tt;
        Xsm[idx] = (t < 2048) ? website[t * LETTERS + k]
                              : payload[(t - 2048) * LETTERS + k];
    }
    __syncthreads();

    const int row = rt * 128 + threadIdx.x;
    const float* wp = W_ih + ((size_t)l * G4 + row) * LETTERS;

    float acc[16];
#pragma unroll
    for (int tt = 0; tt < 16; tt++) acc[tt] = 0.0f;
    for (int k = 0; k < LETTERS; k++) {
        float w = __ldg(wp + k);
#pragma unroll
        for (int tt = 0; tt < 16; tt++) acc[tt] += w * Xsm[tt * LETTERS + k];
    }
    const float bias = b_ih[l * G4 + row] + b_hh[l * G4 + row];
#pragma unroll
    for (int tt = 0; tt < 16; tt++) {
        size_t idx = (((size_t)(t0 + tt)) * LAYERS + l) * G4 + row;
        g_gin[idx] = acc[tt] + bias;
    }

    if (blockIdx.x == 0 && blockIdx.y == 0 && blockIdx.z == 0) {
        // zero both fp16 h buffers (2 * 1024 halfs = 4KB = 256 uint4)
        for (int i = threadIdx.x; i < 256; i += 128) {
            uint4 z = {0u, 0u, 0u, 0u};
            ((uint4*)g_hh)[i] = z;
        }
        if (threadIdx.x < NLINES) g_ctrs[threadIdx.x].v = 0;
        if (threadIdx.x == 0) g_fin = 0;
    }
}

// ---------------------------------------------------------------------------
// Phase 1b: repack W_hh fp32 [l][row][k] into mma.m16n8k16 A-fragment layout
// (verified in R8).
// ---------------------------------------------------------------------------
__global__ void repack_whh_kernel(const float* __restrict__ W_hh) {
    size_t idx = (size_t)blockIdx.x * 1024 + threadIdx.x;   // over 8*4096*1024
    int k   = (int)(idx & 1023);
    size_t rowl = idx >> 10;
    int row = (int)(rowl & 4095);
    int l   = (int)(rowl >> 12);

    int g  = row >> 10, rem = row & 1023, bb = rem >> 3, j = rem & 7;
    int r  = g * 8 + j;                 // 0..31
    int mt = r >> 4, rr = r & 15;
    int groupID = rr & 7, rowhalf = rr >> 3;

    int w  = k >> 7, krem = k & 127;
    int kt = krem >> 4, kk = krem & 15;
    int khalf = kk >> 3, tg = (kk & 7) >> 1, oddk = kk & 1;

    int comp = khalf * 2 + rowhalf;     // 0=.x 1=.y 2=.z 3=.w
    int lane = groupID * 4 + tg;
    int t    = mt * 8 + kt;

    size_t base = ((size_t)(l * NCTA) + bb) * 32768;   // halfs per (l,bb)
    size_t dst  = base + ((size_t)(w * 16 + t) * 32 + lane) * 8 + comp * 2 + oddk;
    g_w2[dst] = __float2half(W_hh[idx]);
}

// ---------------------------------------------------------------------------
// Phase 2: persistent recurrent kernel. 128 CTAs x 256 threads.
// Warp w polls barrier line w (CTAs [16w,16w+16)), fetches that group's 256B
// fp16 h-segment — which is exactly warp w's mma K-chunk — and starts its
// 16 HMMA without a block-wide sync. Full-CTA convergence at the psum sync.
// ---------------------------------------------------------------------------
__global__ void __launch_bounds__(TPB, 1)
lstm_kernel(const float* __restrict__ W_lin,
            const float* __restrict__ b_lin,
            const float* __restrict__ W_out,
            const float* __restrict__ b_out,
            float* __restrict__ out) {
    __shared__ __align__(16) __half h_half[HIDDEN];   // fp16 hidden state
    __shared__ float psum_sm[32 * 9];                 // [row][warp], pitch 9
    __shared__ float gin_sm[2][32];
    __shared__ __align__(16) __half hn_half[8];
    __shared__ float feat_sm[16];
    extern __shared__ __align__(16) uint4 w_sm[];     // SMEM_LAYERS * 4096 uint4

    const int tid  = threadIdx.x;
    const int bb   = blockIdx.x;
    const int w    = tid >> 5;
    const int lane = tid & 31;
    const int tg   = lane & 3;

    const uint4* __restrict__ wglob = (const uint4*)g_w2;
    const size_t block_u4 = 4096;                     // uint4 per (l,bb)
    unsigned* const my_ctr = &g_ctrs[bb >> 4].v;      // group = bb>>4

    // ---- copy layers 0..2 of this CTA's weights into smem (once) ----
    for (int l = 0; l < SMEM_LAYERS; l++) {
        const uint4* s = wglob + ((size_t)(l * NCTA) + bb) * block_u4;
#pragma unroll
        for (int i = tid; i < 4096; i += TPB)
            w_sm[l * 4096 + i] = __ldg(&s[i]);
    }
    __syncthreads();

    // ---- prologue: fragments + gin for cell 0 ----
    uint4 wreg[16];
    {
        const uint4* wrow = w_sm + 0 * 4096 + w * 512;   // layer 0 smem-resident
#pragma unroll
        for (int t = 0; t < 16; t++) wreg[t] = wrow[t * 32 + lane];
    }
    if (tid < 32)
        gin_sm[0][tid] = __ldcs(&g_gin[(size_t)0 * G4
                                       + (tid >> 3) * HIDDEN + bb * 8 + (tid & 7)]);

    float c = 0.0f;   // threads 0-7 own c[bb*8+tid]

    for (int cell = 0; cell < NCELLS; cell++) {
        const int slot = cell & 1;

        // ---- warp w: wait for its group, fetch its 256B h-segment ----
        if (lane == 0) {
            const unsigned target = (unsigned)CTAS_PER_LINE * (unsigned)cell;
            while (ld_acquire_u32(&g_ctrs[w].v) < target) { }
        }
        __syncwarp();
        {
            uint2 seg = __ldcg(((const uint2*)&g_hh[slot][w * 128]) + lane);
            *(uint2*)&h_half[w * 128 + lane * 4] = seg;
        }
        __syncwarp();

        // ---- 16 HMMA: rows 0..31 x K-chunk [w*128, w*128+128) ----
        float d0[4] = {0.f, 0.f, 0.f, 0.f};
        float d1[4] = {0.f, 0.f, 0.f, 0.f};
        const unsigned* hb = (const unsigned*)h_half;
#pragma unroll
        for (int kt = 0; kt < 8; kt++) {
            const int kbase = w * 128 + kt * 16;
            unsigned b0 = hb[(kbase >> 1) + tg];
            unsigned b1 = hb[(kbase >> 1) + 4 + tg];
            mma_16x8x16(d0[0], d0[1], d0[2], d0[3], wreg[kt], b0, b1);
            mma_16x8x16(d1[0], d1[1], d1[2], d1[3], wreg[8 + kt], b0, b1);
        }

        // ---- prefetch next cell's fragments (drain overlaps reduce/publish/poll) ----
        {
            const int nx = (cell + 1 < NCELLS) ? cell + 1 : 0;
            const int ln = nx & 7;
            if (ln < SMEM_LAYERS) {
                const uint4* wrow = w_sm + ln * 4096 + w * 512;
#pragma unroll
                for (int t = 0; t < 16; t++) wreg[t] = wrow[t * 32 + lane];
            } else {
                const uint4* wrow = wglob + ((size_t)(ln * NCTA) + bb) * block_u4 + w * 512;
#pragma unroll
                for (int t = 0; t < 16; t++) wreg[t] = __ldg(&wrow[t * 32 + lane]);
            }
        }

        // ---- col-0 partials to psum ----
        if (tg == 0) {
            const int gID = lane >> 2;
            psum_sm[(gID) * 9 + w]      = d0[0];
            psum_sm[(gID + 8) * 9 + w]  = d0[2];
            psum_sm[(gID + 16) * 9 + w] = d1[0];
            psum_sm[(gID + 24) * 9 + w] = d1[2];
        }
        __syncthreads();   // full-CTA convergence (the real barrier)

        // ---- warp 0: gin prefetch (n+1), K-reduce, gates, publish ----
        if (tid < 32) {
            const int nx = (cell + 1 < NCELLS) ? cell + 1 : 0;
            gin_sm[slot ^ 1][lane] = __ldcs(&g_gin[(size_t)nx * G4
                                            + (lane >> 3) * HIDDEN + bb * 8 + (lane & 7)]);

            const float* pr = &psum_sm[lane * 9];
            float s = ((pr[0] + pr[1]) + (pr[2] + pr[3]))
                    + ((pr[4] + pr[5]) + (pr[6] + pr[7]));
            float v1 = __shfl_sync(0xffffffffu, s, (lane & 7) + 8);
            float v2 = __shfl_sync(0xffffffffu, s, (lane & 7) + 16);
            float v3 = __shfl_sync(0xffffffffu, s, (lane & 7) + 24);
            if (lane < 8) {
                float iv = sigmoid_fast(s  + gin_sm[slot][lane]);
                float fv = sigmoid_fast(v1 + gin_sm[slot][8 + lane]);
                float gv = tanh_approx (v2 + gin_sm[slot][16 + lane]);
                float ov = sigmoid_fast(v3 + gin_sm[slot][24 + lane]);
                c = fv * c + iv * gv;
                hn_half[lane] = __float2half(ov * tanh_approx(c));
            }
            __syncwarp();
            if (lane == 0) {
                uint4 v = *(const uint4*)hn_half;           // 8 fp16 = 16B
                *(uint4*)&g_hh[slot ^ 1][bb * 8] = v;       // publish h
                red_release_add(my_ctr, 1u);                // release orders the store
            }
        }
    }

    // ---- publish final c, final-round counter, epilogue on CTA 0 ----
    if (tid < 8) g_c[bb * 8 + tid] = c;
    if (tid < 32) {
        __syncwarp();
        if (tid == 0) {
            __threadfence();
            red_release_add(&g_fin, 1u);
        }
    }

    if (bb == 0) {
        if (tid == 0) {
            while (ld_acquire_u32(&g_fin) < (unsigned)NCTA) { }
        }
        __syncthreads();
        if (tid < 16) {
            const float* wl = W_lin + tid * HIDDEN;
            float a = b_lin[tid];
            for (int k = 0; k < HIDDEN; k++) a += wl[k] * __ldcg(&g_c[k]);
            feat_sm[tid] = a;
        }
        __syncthreads();
        if (tid == 0) {
            float sum = b_out[0];
#pragma unroll
            for (int k = 0; k < 16; k++) sum += W_out[k] * feat_sm[k];
            out[0] = 1.0f / (1.0f + expf(-sum));
        }
    }
}

// ---------------------------------------------------------------------------
// Harness entry. Inputs: 0 website, 1 payload, 2 W_ih, 3 W_hh, 4 b_ih,
// 5 b_hh, 6 W_lin, 7 b_lin, 8 W_out, 9 b_out
// ---------------------------------------------------------------------------
extern "C" void kernel_launch(void* const* d_in, const int* in_sizes, int n_in,
                              void* d_out, int out_size) {
    const float* website = (const float*)d_in[0];
    const float* payload = (const float*)d_in[1];
    const float* W_ih    = (const float*)d_in[2];
    const float* W_hh    = (const float*)d_in[3];
    const float* b_ih    = (const float*)d_in[4];
    const float* b_hh    = (const float*)d_in[5];
    const float* W_lin   = (const float*)d_in[6];
    const float* b_lin   = (const float*)d_in[7];
    const float* W_out   = (const float*)d_in[8];
    const float* b_out   = (const float*)d_in[9];
    float* out = (float*)d_out;

    static int attr_set = 0;
    if (!attr_set) {
        cudaFuncSetAttribute(lstm_kernel,
                             cudaFuncAttributeMaxDynamicSharedMemorySize,
                             WSMEM_BYTES);
        attr_set = 1;
    }

    dim3 grid1(32, 8, 256);
    precompute_kernel<<<grid1, 128>>>(website, payload, W_ih, b_ih, b_hh);
    repack_whh_kernel<<<(LAYERS * G4 * HIDDEN) / 1024, 1024>>>(W_hh);
    lstm_kernel<<<NCTA, TPB, WSMEM_BYTES>>>(W_lin, b_lin, W_out, b_out, out);
}

// round 16
// speedup vs baseline: 1.6129x; 1.6129x over previous
#include <cuda_runtime.h>
#include <cuda_fp16.h>

// Problem constants
#define T_TOTAL 4096
#define LAYERS  8
#define HIDDEN  1024
#define G4      4096
#define LETTERS 100
#define NCTA    128
#define TPB     256
#define NCELLS  (T_TOTAL * LAYERS)   // 32768
#define SMEM_LAYERS 3
#define WSMEM_BYTES (SMEM_LAYERS * 32 * HIDDEN * 2)   // 196608
#define NLINES  8
#define CTAS_PER_LINE (NCTA / NLINES)   // 16

// ---------------------------------------------------------------------------
// Device scratch
// ---------------------------------------------------------------------------
__device__ float g_gin[(size_t)T_TOTAL * LAYERS * G4];          // 512 MB input projections
__device__ __half g_w2[(size_t)LAYERS * NCTA * 32 * HIDDEN];    // 64 MB fp16 W_hh, mma A-fragment layout
__device__ __align__(16) __half g_hh[2][NCTA * 8];              // fp16 hidden state, parity buffered
__device__ __align__(16) float g_c[HIDDEN];                     // final cell state
__device__ unsigned g_fin;                                      // final-round counter

struct __align__(128) CtrLine { unsigned v; unsigned pad[31]; };
__device__ CtrLine g_ctrs[NLINES];   // line L counts CTAs with (bb & 7) == L

__device__ __forceinline__ unsigned ld_acquire_u32(const unsigned* p) {
    unsigned v;
    asm volatile("ld.acquire.gpu.global.u32 %0, [%1];" : "=r"(v) : "l"(p) : "memory");
    return v;
}
__device__ __forceinline__ void red_release_add(unsigned* p, unsigned v) {
    asm volatile("red.release.gpu.global.add.u32 [%0], %1;" :: "l"(p), "r"(v) : "memory");
}
__device__ __forceinline__ float tanh_approx(float x) {
    float y;
    asm("tanh.approx.f32 %0, %1;" : "=f"(y) : "f"(x));
    return y;
}
__device__ __forceinline__ float sigmoid_fast(float x) {
    return 0.5f + 0.5f * tanh_approx(0.5f * x);
}
__device__ __forceinline__ void mma_16x8x16(float& d0, float& d1, float& d2, float& d3,
                                            uint4 a, unsigned b0, unsigned b1) {
    asm volatile(
        "mma.sync.aligned.m16n8k16.row.col.f32.f16.f16.f32 "
        "{%0,%1,%2,%3}, {%4,%5,%6,%7}, {%8,%9}, {%0,%1,%2,%3};"
        : "+f"(d0), "+f"(d1), "+f"(d2), "+f"(d3)
        : "r"(a.x), "r"(a.y), "r"(a.z), "r"(a.w), "r"(b0), "r"(b1));
}

// ---------------------------------------------------------------------------
// Phase 1a: gin[cell][row] = W_ih@x_t + b_ih + b_hh; reset state.
// ---------------------------------------------------------------------------
__global__ void precompute_kernel(const float* __restrict__ website,
                                  const float* __restrict__ payload,
                                  const float* __restrict__ W_ih,
                                  const float* __restrict__ b_ih,
                                  const float* __restrict__ b_hh) {
    __shared__ float Xsm[16 * LETTERS];
    const int rt = blockIdx.x;
    const int l  = blockIdx.y;
    const int t0 = blockIdx.z * 16;

    for (int idx = threadIdx.x; idx < 16 * LETTERS; idx += 128) {
        int tt = idx / LETTERS, k = idx % LETTERS;
        int t = t0 + tt;
        Xsm[idx] = (t < 2048) ? website[t * LETTERS + k]
                              : payload[(t - 2048) * LETTERS + k];
    }
    __syncthreads();

    const int row = rt * 128 + threadIdx.x;
    const float* wp = W_ih + ((size_t)l * G4 + row) * LETTERS;

    float acc[16];
#pragma unroll
    for (int tt = 0; tt < 16; tt++) acc[tt] = 0.0f;
    for (int k = 0; k < LETTERS; k++) {
        float w = __ldg(wp + k);
#pragma unroll
        for (int tt = 0; tt < 16; tt++) acc[tt] += w * Xsm[tt * LETTERS + k];
    }
    const float bias = b_ih[l * G4 + row] + b_hh[l * G4 + row];
#pragma unroll
    for (int tt = 0; tt < 16; tt++) {
        size_t idx = (((size_t)(t0 + tt)) * LAYERS + l) * G4 + row;
        g_gin[idx] = acc[tt] + bias;
    }

    if (blockIdx.x == 0 && blockIdx.y == 0 && blockIdx.z == 0) {
        // zero both fp16 h buffers (2 * 1024 halfs = 4KB = 256 uint4)
        for (int i = threadIdx.x; i < 256; i += 128) {
            uint4 z = {0u, 0u, 0u, 0u};
            ((uint4*)g_hh)[i] = z;
        }
        if (threadIdx.x < NLINES) g_ctrs[threadIdx.x].v = 0;
        if (threadIdx.x == 0) g_fin = 0;
    }
}

// ---------------------------------------------------------------------------
// Phase 1b: repack W_hh fp32 [l][row][k] into mma.m16n8k16 A-fragment layout
// (verified in R8).
// ---------------------------------------------------------------------------
__global__ void repack_whh_kernel(const float* __restrict__ W_hh) {
    size_t idx = (size_t)blockIdx.x * 1024 + threadIdx.x;   // over 8*4096*1024
    int k   = (int)(idx & 1023);
    size_t rowl = idx >> 10;
    int row = (int)(rowl & 4095);
    int l   = (int)(rowl >> 12);

    int g  = row >> 10, rem = row & 1023, bb = rem >> 3, j = rem & 7;
    int r  = g * 8 + j;                 // 0..31
    int mt = r >> 4, rr = r & 15;
    int groupID = rr & 7, rowhalf = rr >> 3;

    int w  = k >> 7, krem = k & 127;
    int kt = krem >> 4, kk = krem & 15;
    int khalf = kk >> 3, tg = (kk & 7) >> 1, oddk = kk & 1;

    int comp = khalf * 2 + rowhalf;     // 0=.x 1=.y 2=.z 3=.w
    int lane = groupID * 4 + tg;
    int t    = mt * 8 + kt;

    size_t base = ((size_t)(l * NCTA) + bb) * 32768;   // halfs per (l,bb)
    size_t dst  = base + ((size_t)(w * 16 + t) * 32 + lane) * 8 + comp * 2 + oddk;
    g_w2[dst] = __float2half(W_hh[idx]);
}

// ---------------------------------------------------------------------------
// Phase 2: persistent recurrent kernel (R8 sync skeleton).
// Weight refill happens AFTER the mma consumed the fragments, during the
// gates phase, keeping the L1tex FIFO clear ahead of the poll and h load.
// ---------------------------------------------------------------------------
__global__ void __launch_bounds__(TPB, 1)
lstm_kernel(const float* __restrict__ W_lin,
            const float* __restrict__ b_lin,
            const float* __restrict__ W_out,
            const float* __restrict__ b_out,
            float* __restrict__ out) {
    __shared__ __align__(16) __half h_half[HIDDEN];   // fp16 hidden state
    __shared__ float psum_sm[32 * 9];                 // [row][warp], pitch 9
    __shared__ float gin_sm[2][32];
    __shared__ __align__(16) __half hn_half[8];
    __shared__ float feat_sm[16];
    extern __shared__ __align__(16) uint4 w_sm[];     // SMEM_LAYERS * 4096 uint4

    const int tid  = threadIdx.x;
    const int bb   = blockIdx.x;
    const int w    = tid >> 5;
    const int lane = tid & 31;
    const int tg   = lane & 3;

    const uint4* __restrict__ wglob = (const uint4*)g_w2;
    const size_t block_u4 = 4096;                     // uint4 per (l,bb)
    unsigned* const my_ctr = &g_ctrs[bb & (NLINES - 1)].v;

    // ---- copy layers 0..2 of this CTA's weights into smem (once) ----
    for (int l = 0; l < SMEM_LAYERS; l++) {
        const uint4* s = wglob + ((size_t)(l * NCTA) + bb) * block_u4;
#pragma unroll
        for (int i = tid; i < 4096; i += TPB)
            w_sm[l * 4096 + i] = __ldg(&s[i]);
    }
    __syncthreads();

    // ---- prologue: fragments + gin for cell 0 ----
    uint4 wreg[16];
    {
        const uint4* wrow = w_sm + 0 * 4096 + w * 512;   // layer 0 smem-resident
#pragma unroll
        for (int t = 0; t < 16; t++) wreg[t] = wrow[t * 32 + lane];
    }
    if (tid < 32)
        gin_sm[0][tid] = __ldcs(&g_gin[(size_t)0 * G4
                                       + (tid >> 3) * HIDDEN + bb * 8 + (tid & 7)]);

    float c = 0.0f;   // threads 0-7 own c[bb*8+tid]

    for (int cell = 0; cell < NCELLS; cell++) {
        const int slot = cell & 1;

        // ---- spread-counter barrier: 8 pollers, queue is clear by now ----
        if (tid < NLINES) {
            const unsigned target = (unsigned)CTAS_PER_LINE * (unsigned)cell;
            while (ld_acquire_u32(&g_ctrs[tid].v) < target) { }
        }
        __syncthreads();

        // ---- load fp16 h (2KB = 128 x uint4) ----
        if (tid < 128)
            ((uint4*)h_half)[tid] = __ldcg(&((const uint4*)g_hh[slot])[tid]);
        __syncthreads();

        // ---- 16 HMMA per warp: rows 0..31 x K-chunk [w*128, w*128+128) ----
        float d0[4] = {0.f, 0.f, 0.f, 0.f};
        float d1[4] = {0.f, 0.f, 0.f, 0.f};
        const unsigned* hb = (const unsigned*)h_half;
#pragma unroll
        for (int kt = 0; kt < 8; kt++) {
            const int kbase = w * 128 + kt * 16;
            unsigned b0 = hb[(kbase >> 1) + tg];
            unsigned b1 = hb[(kbase >> 1) + 4 + tg];
            mma_16x8x16(d0[0], d0[1], d0[2], d0[3], wreg[kt], b0, b1);
            mma_16x8x16(d1[0], d1[1], d1[2], d1[3], wreg[8 + kt], b0, b1);
        }

        // ---- col-0 partials to psum ----
        if (tg == 0) {
            const int gID = lane >> 2;
            psum_sm[(gID) * 9 + w]      = d0[0];
            psum_sm[(gID + 8) * 9 + w]  = d0[2];
            psum_sm[(gID + 16) * 9 + w] = d1[0];
            psum_sm[(gID + 24) * 9 + w] = d1[2];
        }
        __syncthreads();

        const int nx = (cell + 1 < NCELLS) ? cell + 1 : 0;
        const int ln = nx & 7;

        // ---- warps 1..7: refill wreg for next cell (drains during gates) ----
        if (w != 0) {
            if (ln < SMEM_LAYERS) {
                const uint4* wrow = w_sm + ln * 4096 + w * 512;
#pragma unroll
                for (int t = 0; t < 16; t++) wreg[t] = wrow[t * 32 + lane];
            } else {
                const uint4* wrow = wglob + ((size_t)(ln * NCTA) + bb) * block_u4 + w * 512;
#pragma unroll
                for (int t = 0; t < 16; t++) wreg[t] = __ldg(&wrow[t * 32 + lane]);
            }
        }

        // ---- warp 0: K-reduce, gates, publish, arrive — THEN its refills ----
        if (tid < 32) {
            const float* pr = &psum_sm[lane * 9];
            float s = ((pr[0] + pr[1]) + (pr[2] + pr[3]))
                    + ((pr[4] + pr[5]) + (pr[6] + pr[7]));
            float v1 = __shfl_sync(0xffffffffu, s, (lane & 7) + 8);
            float v2 = __shfl_sync(0xffffffffu, s, (lane & 7) + 16);
            float v3 = __shfl_sync(0xffffffffu, s, (lane & 7) + 24);
            if (lane < 8) {
                float iv = sigmoid_fast(s  + gin_sm[slot][lane]);
                float fv = sigmoid_fast(v1 + gin_sm[slot][8 + lane]);
                float gv = tanh_approx (v2 + gin_sm[slot][16 + lane]);
                float ov = sigmoid_fast(v3 + gin_sm[slot][24 + lane]);
                c = fv * c + iv * gv;
                hn_half[lane] = __float2half(ov * tanh_approx(c));
            }
            __syncwarp();
            if (lane == 0) {
                uint4 v = *(const uint4*)hn_half;           // 8 fp16 = 16B
                *(uint4*)&g_hh[slot ^ 1][bb * 8] = v;       // publish h
                red_release_add(my_ctr, 1u);                // release orders the store
            }
            __syncwarp();

            // gin prefetch for next cell (after the arrive)
            gin_sm[slot ^ 1][lane] = __ldcs(&g_gin[(size_t)nx * G4
                                            + (lane >> 3) * HIDDEN + bb * 8 + (lane & 7)]);
            // warp 0's own wreg refill
            if (ln < SMEM_LAYERS) {
                const uint4* wrow = w_sm + ln * 4096 + 0 * 512;
#pragma unroll
                for (int t = 0; t < 16; t++) wreg[t] = wrow[t * 32 + lane];
            } else {
                const uint4* wrow = wglob + ((size_t)(ln * NCTA) + bb) * block_u4 + 0 * 512;
#pragma unroll
                for (int t = 0; t < 16; t++) wreg[t] = __ldg(&wrow[t * 32 + lane]);
            }
        }
    }

    // ---- publish final c, final-round counter, epilogue on CTA 0 ----
    if (tid < 8) g_c[bb * 8 + tid] = c;
    if (tid < 32) {
        __syncwarp();
        if (tid == 0) {
            __threadfence();
            red_release_add(&g_fin, 1u);
        }
    }

    if (bb == 0) {
        if (tid == 0) {
            while (ld_acquire_u32(&g_fin) < (unsigned)NCTA) { }
        }
        __syncthreads();
        if (tid < 16) {
            const float* wl = W_lin + tid * HIDDEN;
            float a = b_lin[tid];
            for (int k = 0; k < HIDDEN; k++) a += wl[k] * __ldcg(&g_c[k]);
            feat_sm[tid] = a;
        }
        __syncthreads();
        if (tid == 0) {
            float sum = b_out[0];
#pragma unroll
            for (int k = 0; k < 16; k++) sum += W_out[k] * feat_sm[k];
            out[0] = 1.0f / (1.0f + expf(-sum));
        }
    }
}

// ---------------------------------------------------------------------------
// Harness entry. Inputs: 0 website, 1 payload, 2 W_ih, 3 W_hh, 4 b_ih,
// 5 b_hh, 6 W_lin, 7 b_lin, 8 W_out, 9 b_out
// ---------------------------------------------------------------------------
extern "C" void kernel_launch(void* const* d_in, const int* in_sizes, int n_in,
                              void* d_out, int out_size) {
    const float* website = (const float*)d_in[0];
    const float* payload = (const float*)d_in[1];
    const float* W_ih    = (const float*)d_in[2];
    const float* W_hh    = (const float*)d_in[3];
    const float* b_ih    = (const float*)d_in[4];
    const float* b_hh    = (const float*)d_in[5];
    const float* W_lin   = (const float*)d_in[6];
    const float* b_lin   = (const float*)d_in[7];
    const float* W_out   = (const float*)d_in[8];
    const float* b_out   = (const float*)d_in[9];
    float* out = (float*)d_out;

    static int attr_set = 0;
    if (!attr_set) {
        cudaFuncSetAttribute(lstm_kernel,
                             cudaFuncAttributeMaxDynamicSharedMemorySize,
                             WSMEM_BYTES);
        attr_set = 1;
    }

    dim3 grid1(32, 8, 256);
    precompute_kernel<<<grid1, 128>>>(website, payload, W_ih, b_ih, b_hh);
    repack_whh_kernel<<<(LAYERS * G4 * HIDDEN) / 1024, 1024>>>(W_hh);
    lstm_kernel<<<NCTA, TPB, WSMEM_BYTES>>>(W_lin, b_lin, W_out, b_out, out);
}

// round 17
// speedup vs baseline: 1.6595x; 1.0289x over previous
#include <cuda_runtime.h>
#include <cuda_fp16.h>

// Problem constants
#define T_TOTAL 4096
#define LAYERS  8
#define HIDDEN  1024
#define G4      4096
#define LETTERS 100
#define NCTA    128
#define TPB     256
#define NCELLS  (T_TOTAL * LAYERS)   // 32768
#define SMEM_LAYERS 6                // int8: 6 layers x 32KB = 192KB
#define WSMEM_BYTES (SMEM_LAYERS * 32 * HIDDEN)   // 196608
#define NLINES  8
#define CTAS_PER_LINE (NCTA / NLINES)   // 16

// ---------------------------------------------------------------------------
// Device scratch
// ---------------------------------------------------------------------------
__device__ float g_gin[(size_t)T_TOTAL * LAYERS * G4];          // 512 MB input projections
__device__ unsigned char g_w1[(size_t)LAYERS * NCTA * 32 * HIDDEN]; // 32 MB int8 W_hh (biased, fragment layout)
__device__ float g_wscale[LAYERS * NCTA * 32];                  // per-row quant scales
__device__ __align__(16) __half g_hh[2][NCTA * 8];              // fp16 hidden state, parity buffered
__device__ __align__(16) float g_c[HIDDEN];                     // final cell state
__device__ unsigned g_fin;                                      // final-round counter

struct __align__(128) CtrLine { unsigned v; unsigned pad[31]; };
__device__ CtrLine g_ctrs[NLINES];

__device__ __forceinline__ unsigned ld_acquire_u32(const unsigned* p) {
    unsigned v;
    asm volatile("ld.acquire.gpu.global.u32 %0, [%1];" : "=r"(v) : "l"(p) : "memory");
    return v;
}
__device__ __forceinline__ void red_release_add(unsigned* p, unsigned v) {
    asm volatile("red.release.gpu.global.add.u32 [%0], %1;" :: "l"(p), "r"(v) : "memory");
}
__device__ __forceinline__ float tanh_approx(float x) {
    float y;
    asm("tanh.approx.f32 %0, %1;" : "=f"(y) : "f"(x));
    return y;
}
__device__ __forceinline__ float sigmoid_fast(float x) {
    return 0.5f + 0.5f * tanh_approx(0.5f * x);
}
__device__ __forceinline__ void mma_16x8x16(float& d0, float& d1, float& d2, float& d3,
                                            uint4 a, unsigned b0, unsigned b1) {
    asm volatile(
        "mma.sync.aligned.m16n8k16.row.col.f32.f16.f16.f32 "
        "{%0,%1,%2,%3}, {%4,%5,%6,%7}, {%8,%9}, {%0,%1,%2,%3};"
        : "+f"(d0), "+f"(d1), "+f"(d2), "+f"(d3)
        : "r"(a.x), "r"(a.y), "r"(a.z), "r"(a.w), "r"(b0), "r"(b1));
}

// int8->fp16 dequant: byte b stored biased (q+128); 0x6400|b as fp16 = 1024+b;
// value = s*(b-128) = fma(1024+b, s, -1152*s).
__device__ __forceinline__ unsigned dq_lo2(unsigned wd, __half2 s, __half2 b) {
    unsigned r = __byte_perm(wd, 0x64646464u, 0x4140);
    __half2 h = __hfma2(*(__half2*)&r, s, b);
    return *(unsigned*)&h;
}
__device__ __forceinline__ unsigned dq_hi2(unsigned wd, __half2 s, __half2 b) {
    unsigned r = __byte_perm(wd, 0x64646464u, 0x4342);
    __half2 h = __hfma2(*(__half2*)&r, s, b);
    return *(unsigned*)&h;
}

// Expand 128 raw bytes (8 uint4) into 16 fp16 mma A-fragments with per-row scales.
__device__ __forceinline__ void expand_frags(const uint4 raw[8], const float s4[4],
                                             uint4 wreg[16]) {
    __half2 sc[4], bi[4];
#pragma unroll
    for (int i = 0; i < 4; i++) {
        float s = s4[i];
        sc[i] = __floats2half2_rn(s, s);
        float nb = -1152.0f * s;
        bi[i] = __floats2half2_rn(nb, nb);
    }
#pragma unroll
    for (int t = 0; t < 16; t++) {
        uint4 rw = raw[t >> 1];
        unsigned wA = (t & 1) ? rw.z : rw.x;
        unsigned wB = (t & 1) ? rw.w : rw.y;
        int si = (t >> 3) * 2;
        wreg[t].x = dq_lo2(wA, sc[si], bi[si]);
        wreg[t].y = dq_hi2(wA, sc[si + 1], bi[si + 1]);
        wreg[t].z = dq_lo2(wB, sc[si], bi[si]);
        wreg[t].w = dq_hi2(wB, sc[si + 1], bi[si + 1]);
    }
}

// ---------------------------------------------------------------------------
// Phase 1a: gin[cell][row] = W_ih@x_t + b_ih + b_hh; reset state.
// ---------------------------------------------------------------------------
__global__ void precompute_kernel(const float* __restrict__ website,
                                  const float* __restrict__ payload,
                                  const float* __restrict__ W_ih,
                                  const float* __restrict__ b_ih,
                                  const float* __restrict__ b_hh) {
    __shared__ float Xsm[16 * LETTERS];
    const int rt = blockIdx.x;
    const int l  = blockIdx.y;
    const int t0 = blockIdx.z * 16;

    for (int idx = threadIdx.x; idx < 16 * LETTERS; idx += 128) {
        int tt = idx / LETTERS, k = idx % LETTERS;
        int t = t0 + tt;
        Xsm[idx] = (t < 2048) ? website[t * LETTERS + k]
                              : payload[(t - 2048) * LETTERS + k];
    }
    __syncthreads();

    const int row = rt * 128 + threadIdx.x;
    const float* wp = W_ih + ((size_t)l * G4 + row) * LETTERS;

    float acc[16];
#pragma unroll
    for (int tt = 0; tt < 16; tt++) acc[tt] = 0.0f;
    for (int k = 0; k < LETTERS; k++) {
        float w = __ldg(wp + k);
#pragma unroll
        for (int tt = 0; tt < 16; tt++) acc[tt] += w * Xsm[tt * LETTERS + k];
    }
    const float bias = b_ih[l * G4 + row] + b_hh[l * G4 + row];
#pragma unroll
    for (int tt = 0; tt < 16; tt++) {
        size_t idx = (((size_t)(t0 + tt)) * LAYERS + l) * G4 + row;
        g_gin[idx] = acc[tt] + bias;
    }

    if (blockIdx.x == 0 && blockIdx.y == 0 && blockIdx.z == 0) {
        for (int i = threadIdx.x; i < 256; i += 128) {
            uint4 z = {0u, 0u, 0u, 0u};
            ((uint4*)g_hh)[i] = z;
        }
        if (threadIdx.x < NLINES) g_ctrs[threadIdx.x].v = 0;
        if (threadIdx.x == 0) g_fin = 0;
    }
}

// ---------------------------------------------------------------------------
// Phase 1b-1: per-row quant scales. Block (bb,l); warp handles rows w+8i.
// ---------------------------------------------------------------------------
__global__ void scale_kernel(const float* __restrict__ W_hh) {
    const int bb = blockIdx.x;
    const int l  = blockIdx.y;
    const int w  = threadIdx.x >> 5;
    const int lane = threadIdx.x & 31;

    for (int i = 0; i < 4; i++) {
        int r = w + 8 * i;                       // 0..31
        int row_g = (r >> 3) * 1024 + bb * 8 + (r & 7);
        const float* wp = W_hh + ((size_t)l * G4 + row_g) * HIDDEN;
        float m = 0.0f;
        for (int kk = 0; kk < 32; kk++)
            m = fmaxf(m, fabsf(wp[lane + 32 * kk]));
#pragma unroll
        for (int s = 16; s > 0; s >>= 1)
            m = fmaxf(m, __shfl_xor_sync(0xffffffffu, m, s));
        if (lane == 0)
            g_wscale[(l * NCTA + bb) * 32 + r] = fmaxf(m, 1e-30f) / 127.0f;
    }
}

// ---------------------------------------------------------------------------
// Phase 1b-2: repack W_hh fp32 -> biased int8 in thread-contiguous fragment
// byte layout: byte = base(l,bb) + (w*256 + (t>>1)*32 + lane)*16
//                    + (t&1)*8 + comp*2 + oddk
// ---------------------------------------------------------------------------
__global__ void repack_whh_kernel(const float* __restrict__ W_hh) {
    size_t idx = (size_t)blockIdx.x * 1024 + threadIdx.x;   // over 8*4096*1024
    int k   = (int)(idx & 1023);
    size_t rowl = idx >> 10;
    int row = (int)(rowl & 4095);
    int l   = (int)(rowl >> 12);

    int g  = row >> 10, rem = row & 1023, bb = rem >> 3, j = rem & 7;
    int r  = g * 8 + j;                 // 0..31
    int mt = r >> 4, rr = r & 15;
    int groupID = rr & 7, rowhalf = rr >> 3;

    int w  = k >> 7, krem = k & 127;
    int kt = krem >> 4, kk = krem & 15;
    int khalf = kk >> 3, tg = (kk & 7) >> 1, oddk = kk & 1;

    int comp = khalf * 2 + rowhalf;     // 0=.x 1=.y 2=.z 3=.w
    int lane = groupID * 4 + tg;
    int t    = mt * 8 + kt;

    float s = g_wscale[(l * NCTA + bb) * 32 + r];
    int q = __float2int_rn(W_hh[idx] / s) + 128;
    q = min(255, max(0, q));

    size_t base = ((size_t)(l * NCTA) + bb) * 32768;   // bytes per (l,bb)
    size_t dst  = base + ((size_t)(w * 256 + (t >> 1) * 32 + lane)) * 16
                + (t & 1) * 8 + comp * 2 + oddk;
    g_w1[dst] = (unsigned char)q;
}

// ---------------------------------------------------------------------------
// Phase 2: persistent recurrent kernel (R16 skeleton, int8 weights).
// Layers 0..5 in smem; 6..7 via LDG. Raw bytes loaded in the off-path window;
// warps 1..7 dequant in-window, warp 0 (poller) dequants post-h-load.
// ---------------------------------------------------------------------------
__global__ void __launch_bounds__(TPB, 1)
lstm_kernel(const float* __restrict__ W_lin,
            const float* __restrict__ b_lin,
            const float* __restrict__ W_out,
            const float* __restrict__ b_out,
            float* __restrict__ out) {
    __shared__ __align__(16) __half h_half[HIDDEN];
    __shared__ float psum_sm[32 * 9];
    __shared__ float gin_sm[2][32];
    __shared__ __align__(16) __half hn_half[8];
    __shared__ float feat_sm[16];
    __shared__ float scale_sm[LAYERS * 32];
    extern __shared__ __align__(16) uint4 w_sm[];   // SMEM_LAYERS * 2048 uint4

    const int tid  = threadIdx.x;
    const int bb   = blockIdx.x;
    const int w    = tid >> 5;
    const int lane = tid & 31;
    const int tg   = lane & 3;
    const int gid  = lane >> 2;

    const uint4* __restrict__ wglob = (const uint4*)g_w1;
    const size_t block_u4 = 2048;                   // uint4 per (l,bb)
    unsigned* const my_ctr = &g_ctrs[bb & (NLINES - 1)].v;

    // ---- prologue: smem weights (layers 0..5) + scales ----
    for (int i = tid; i < SMEM_LAYERS * 2048; i += TPB)
        w_sm[i] = __ldg(&wglob[((size_t)((i >> 11) * NCTA) + bb) * block_u4 + (i & 2047)]);
    for (int i = tid; i < LAYERS * 32; i += TPB)
        scale_sm[i] = g_wscale[((i >> 5) * NCTA + bb) * 32 + (i & 31)];
    __syncthreads();

    // ---- prologue: raw + fragments + gin for cell 0 (layer 0, smem) ----
    uint4 raw[8];
    float s4[4];
    uint4 wreg[16];
    {
        const uint4* p = w_sm + 0 * 2048 + w * 256;
#pragma unroll
        for (int i = 0; i < 8; i++) raw[i] = p[i * 32 + lane];
#pragma unroll
        for (int i = 0; i < 4; i++) s4[i] = scale_sm[0 * 32 + gid + 8 * i];
        expand_frags(raw, s4, wreg);
    }
    if (tid < 32)
        gin_sm[0][tid] = __ldcs(&g_gin[(size_t)0 * G4
                                       + (tid >> 3) * HIDDEN + bb * 8 + (tid & 7)]);

    float c = 0.0f;   // threads 0-7 own c[bb*8+tid]

    for (int cell = 0; cell < NCELLS; cell++) {
        const int slot = cell & 1;

        // ---- spread-counter barrier: 8 pollers ----
        if (tid < NLINES) {
            const unsigned target = (unsigned)CTAS_PER_LINE * (unsigned)cell;
            while (ld_acquire_u32(&g_ctrs[tid].v) < target) { }
        }
        __syncthreads();

        // ---- load fp16 h (2KB = 128 x uint4) ----
        if (tid < 128)
            ((uint4*)h_half)[tid] = __ldcg(&((const uint4*)g_hh[slot])[tid]);
        __syncthreads();

        // ---- warp 0: deferred dequant (raw arrived during the poll) ----
        if (w == 0) expand_frags(raw, s4, wreg);

        // ---- 16 HMMA per warp: rows 0..31 x K-chunk [w*128, w*128+128) ----
        float d0[4] = {0.f, 0.f, 0.f, 0.f};
        float d1[4] = {0.f, 0.f, 0.f, 0.f};
        const unsigned* hb = (const unsigned*)h_half;
#pragma unroll
        for (int kt = 0; kt < 8; kt++) {
            const int kbase = w * 128 + kt * 16;
            unsigned b0 = hb[(kbase >> 1) + tg];
            unsigned b1 = hb[(kbase >> 1) + 4 + tg];
            mma_16x8x16(d0[0], d0[1], d0[2], d0[3], wreg[kt], b0, b1);
            mma_16x8x16(d1[0], d1[1], d1[2], d1[3], wreg[8 + kt], b0, b1);
        }

        // ---- col-0 partials to psum ----
        if (tg == 0) {
            psum_sm[(gid) * 9 + w]      = d0[0];
            psum_sm[(gid + 8) * 9 + w]  = d0[2];
            psum_sm[(gid + 16) * 9 + w] = d1[0];
            psum_sm[(gid + 24) * 9 + w] = d1[2];
        }
        __syncthreads();

        const int nx = (cell + 1 < NCELLS) ? cell + 1 : 0;
        const int ln = nx & 7;

        // ---- warps 1..7: raw load + dequant in-window ----
        if (w != 0) {
            if (ln < SMEM_LAYERS) {
                const uint4* p = w_sm + ln * 2048 + w * 256;
#pragma unroll
                for (int i = 0; i < 8; i++) raw[i] = p[i * 32 + lane];
            } else {
                const uint4* p = wglob + ((size_t)(ln * NCTA) + bb) * block_u4 + w * 256;
#pragma unroll
                for (int i = 0; i < 8; i++) raw[i] = __ldg(&p[i * 32 + lane]);
            }
#pragma unroll
            for (int i = 0; i < 4; i++) s4[i] = scale_sm[ln * 32 + gid + 8 * i];
            expand_frags(raw, s4, wreg);
        }

        // ---- warp 0: K-reduce, gates, publish, arrive — then raw issue only ----
        if (tid < 32) {
            const float* pr = &psum_sm[lane * 9];
            float s = ((pr[0] + pr[1]) + (pr[2] + pr[3]))
                    + ((pr[4] + pr[5]) + (pr[6] + pr[7]));
            float v1 = __shfl_sync(0xffffffffu, s, (lane & 7) + 8);
            float v2 = __shfl_sync(0xffffffffu, s, (lane & 7) + 16);
            float v3 = __shfl_sync(0xffffffffu, s, (lane & 7) + 24);
            if (lane < 8) {
                float iv = sigmoid_fast(s  + gin_sm[slot][lane]);
                float fv = sigmoid_fast(v1 + gin_sm[slot][8 + lane]);
                float gv = tanh_approx (v2 + gin_sm[slot][16 + lane]);
                float ov = sigmoid_fast(v3 + gin_sm[slot][24 + lane]);
                c = fv * c + iv * gv;
                hn_half[lane] = __float2half(ov * tanh_approx(c));
            }
            __syncwarp();
            if (lane == 0) {
                uint4 v = *(const uint4*)hn_half;
                *(uint4*)&g_hh[slot ^ 1][bb * 8] = v;
                red_release_add(my_ctr, 1u);
            }
            __syncwarp();

            // gin prefetch for next cell (after the arrive)
            gin_sm[slot ^ 1][lane] = __ldcs(&g_gin[(size_t)nx * G4
                                            + (lane >> 3) * HIDDEN + bb * 8 + (lane & 7)]);
            // warp 0's raw load (issue only; dequant deferred past next barrier)
            if (ln < SMEM_LAYERS) {
                const uint4* p = w_sm + ln * 2048 + 0 * 256;
#pragma unroll
                for (int i = 0; i < 8; i++) raw[i] = p[i * 32 + lane];
            } else {
                const uint4* p = wglob + ((size_t)(ln * NCTA) + bb) * block_u4 + 0 * 256;
#pragma unroll
                for (int i = 0; i < 8; i++) raw[i] = __ldg(&p[i * 32 + lane]);
            }
#pragma unroll
            for (int i = 0; i < 4; i++) s4[i] = scale_sm[ln * 32 + gid + 8 * i];
        }
    }

    // ---- publish final c, final-round counter, epilogue on CTA 0 ----
    if (tid < 8) g_c[bb * 8 + tid] = c;
    if (tid < 32) {
        __syncwarp();
        if (tid == 0) {
            __threadfence();
            red_release_add(&g_fin, 1u);
        }
    }

    if (bb == 0) {
        if (tid == 0) {
            while (ld_acquire_u32(&g_fin) < (unsigned)NCTA) { }
        }
        __syncthreads();
        if (tid < 16) {
            const float* wl = W_lin + tid * HIDDEN;
            float a = b_lin[tid];
            for (int k = 0; k < HIDDEN; k++) a += wl[k] * __ldcg(&g_c[k]);
            feat_sm[tid] = a;
        }
        __syncthreads();
        if (tid == 0) {
            float sum = b_out[0];
#pragma unroll
            for (int k = 0; k < 16; k++) sum += W_out[k] * feat_sm[k];
            out[0] = 1.0f / (1.0f + expf(-sum));
        }
    }
}

// ---------------------------------------------------------------------------
// Harness entry. Inputs: 0 website, 1 payload, 2 W_ih, 3 W_hh, 4 b_ih,
// 5 b_hh, 6 W_lin, 7 b_lin, 8 W_out, 9 b_out
// ---------------------------------------------------------------------------
extern "C" void kernel_launch(void* const* d_in, const int* in_sizes, int n_in,
                              void* d_out, int out_size) {
    const float* website = (const float*)d_in[0];
    const float* payload = (const float*)d_in[1];
    const float* W_ih    = (const float*)d_in[2];
    const float* W_hh    = (const float*)d_in[3];
    const float* b_ih    = (const float*)d_in[4];
    const float* b_hh    = (const float*)d_in[5];
    const float* W_lin   = (const float*)d_in[6];
    const float* b_lin   = (const float*)d_in[7];
    const float* W_out   = (const float*)d_in[8];
    const float* b_out   = (const float*)d_in[9];
    float* out = (float*)d_out;

    static int attr_set = 0;
    if (!attr_set) {
        cudaFuncSetAttribute(lstm_kernel,
                             cudaFuncAttributeMaxDynamicSharedMemorySize,
                             WSMEM_BYTES);
        attr_set = 1;
    }

    dim3 grid1(32, 8, 256);
    precompute_kernel<<<grid1, 128>>>(website, payload, W_ih, b_ih, b_hh);
    dim3 grid2(NCTA, LAYERS);
    scale_kernel<<<grid2, 256>>>(W_hh);
    repack_whh_kernel<<<(LAYERS * G4 * HIDDEN) / 1024, 1024>>>(W_hh);
    lstm_kernel<<<NCTA, TPB, WSMEM_BYTES>>>(W_lin, b_lin, W_out, b_out, out);
}